// round 5
// baseline (speedup 1.0000x reference)
#include <cuda_runtime.h>

#define NQ 4
#define NL 2

typedef unsigned long long u64;

// ---------------- packed f32x2 helpers (sm_103a) ----------------
__device__ __forceinline__ u64 pk2(float lo, float hi) {
    u64 r;
    asm("mov.b64 %0, {%1, %2};" : "=l"(r) : "f"(lo), "f"(hi));
    return r;
}
__device__ __forceinline__ void unpk2(u64 v, float& lo, float& hi) {
    asm("mov.b64 {%0, %1}, %2;" : "=f"(lo), "=f"(hi) : "l"(v));
}
__device__ __forceinline__ u64 mul2(u64 a, u64 b) {
    u64 r;
    asm("mul.rn.f32x2 %0, %1, %2;" : "=l"(r) : "l"(a), "l"(b));
    return r;
}
__device__ __forceinline__ u64 fma2(u64 a, u64 b, u64 c) {
    u64 r;
    asm("fma.rn.f32x2 %0, %1, %2, %3;" : "=l"(r) : "l"(a), "l"(b), "l"(c));
    return r;
}

// Batch-invariant constants (both f32x2 lanes duplicated).
//  - Layer-0 RYs in tan form; scalar C'=prod cos(w0/2) folded as C'^2 into coeffs.
//  - Layer-1 RYs absorbed: RY(th)^T Z RY(th) = cos(th) Z - sin(th) X.
struct Consts {
    u64 tp[NQ];    // (+tan(w0_i/2))
    u64 tn[NQ];    // (-tan(w0_i/2))
    u64 h0[16];    // Z-part coeffs, head row 0
    u64 h1[16];    // Z-part coeffs, head row 1
    u64 v0[NQ];    // X-part coeffs, head row 0
    u64 v1[NQ];    // X-part coeffs, head row 1
    u64 b0, b1;
};

__device__ Consts g_scratch;
__constant__ Consts c_consts;

__global__ void setup_kernel(const float* __restrict__ weights,
                             const float* __restrict__ W,
                             const float* __restrict__ b) {
    if (threadIdx.x == 0 && blockIdx.x == 0) {
        float C = 1.0f;
        for (int i = 0; i < NQ; ++i) {
            float h = 0.5f * weights[i];          // layer 0
            float c = cosf(h), s = sinf(h);
            float t = s / c;
            C *= c;
            g_scratch.tp[i] = pk2(t, t);
            g_scratch.tn[i] = pk2(-t, -t);
        }
        float C2 = C * C;
        float c1[NQ], s1[NQ];
        for (int i = 0; i < NQ; ++i) {
            c1[i] = cosf(weights[NQ + i]);        // layer 1, full angle
            s1[i] = sinf(weights[NQ + i]);
        }
        for (int s = 0; s < 16; ++s) {
            float a0 = 0.0f, a1 = 0.0f;
            for (int i = 0; i < NQ; ++i) {
                float sign = ((s >> (3 - i)) & 1) ? -1.0f : 1.0f;
                a0 += W[0 * NQ + i] * c1[i] * sign;
                a1 += W[1 * NQ + i] * c1[i] * sign;
            }
            g_scratch.h0[s] = pk2(C2 * a0, C2 * a0);
            g_scratch.h1[s] = pk2(C2 * a1, C2 * a1);
        }
        for (int i = 0; i < NQ; ++i) {
            float u0 = -2.0f * C2 * W[0 * NQ + i] * s1[i];
            float u1 = -2.0f * C2 * W[1 * NQ + i] * s1[i];
            g_scratch.v0[i] = pk2(u0, u0);
            g_scratch.v1[i] = pk2(u1, u1);
        }
        g_scratch.b0 = pk2(b[0], b[0]);
        g_scratch.b1 = pk2(b[1], b[1]);
    }
}

__device__ __forceinline__ void ry_tan(u64 a[16], int q, u64 tp, u64 tn) {
    const int m = 1 << (3 - q);
#pragma unroll
    for (int idx = 0; idx < 16; ++idx) {
        if (!(idx & m)) {
            u64 a0 = a[idx];
            u64 a1 = a[idx | m];
            a[idx]     = fma2(tn, a1, a0);
            a[idx | m] = fma2(tp, a0, a1);
        }
    }
}

__device__ __forceinline__ void cnot2(u64 a[16], int ctrl, int tgt) {
    const int mc = 1 << (3 - ctrl);
    const int mt = 1 << (3 - tgt);
#pragma unroll
    for (int s = 0; s < 16; ++s) {
        if ((s & mc) && !(s & mt)) {
            u64 tmp = a[s];
            a[s] = a[s | mt];
            a[s | mt] = tmp;
        }
    }
}

// Full per-pair pipeline: angles -> float4 result.
__device__ __forceinline__ float4 sim_pair(float4 xa, float4 xb) {
    float c0a, s0a, c1a, s1a, c2a, s2a, c3a, s3a;
    float c0b, s0b, c1b, s1b, c2b, s2b, c3b, s3b;
    __sincosf(0.5f * xa.x, &s0a, &c0a);
    __sincosf(0.5f * xa.y, &s1a, &c1a);
    __sincosf(0.5f * xa.z, &s2a, &c2a);
    __sincosf(0.5f * xa.w, &s3a, &c3a);
    __sincosf(0.5f * xb.x, &s0b, &c0b);
    __sincosf(0.5f * xb.y, &s1b, &c1b);
    __sincosf(0.5f * xb.z, &s2b, &c2b);
    __sincosf(0.5f * xb.w, &s3b, &c3b);

    u64 c0 = pk2(c0a, c0b), s0 = pk2(s0a, s0b);
    u64 c1 = pk2(c1a, c1b), s1 = pk2(s1a, s1b);
    u64 c2 = pk2(c2a, c2b), s2 = pk2(s2a, s2b);
    u64 c3 = pk2(c3a, c3b), s3 = pk2(s3a, s3b);

    // Product state via tensor expansion (28 muls).
    u64 a[16];
    a[0] = c0;
    a[8] = s0;
    a[4]  = mul2(a[0], s1);  a[12] = mul2(a[8], s1);
    a[0]  = mul2(a[0], c1);  a[8]  = mul2(a[8], c1);
#pragma unroll
    for (int k = 0; k < 16; k += 4) {
        a[k + 2] = mul2(a[k], s2);
        a[k]     = mul2(a[k], c2);
    }
#pragma unroll
    for (int k = 0; k < 16; k += 2) {
        a[k + 1] = mul2(a[k], s3);
        a[k]     = mul2(a[k], c3);
    }

    // Layer 0: CNOT ring (free) + tan-form RYs.
    cnot2(a, 0, 1);
    cnot2(a, 1, 2);
    cnot2(a, 2, 3);
    cnot2(a, 3, 0);
#pragma unroll
    for (int q = 0; q < NQ; ++q) {
        ry_tan(a, q, c_consts.tp[q], c_consts.tn[q]);
    }

    // Layer 1: CNOT ring (free); RYs absorbed into the measurement.
    cnot2(a, 0, 1);
    cnot2(a, 1, 2);
    cnot2(a, 2, 3);
    cnot2(a, 3, 0);

    u64 acc0 = c_consts.b0;
    u64 acc1 = c_consts.b1;
#pragma unroll
    for (int s = 0; s < 16; ++s) {
        u64 p = mul2(a[s], a[s]);
        acc0 = fma2(c_consts.h0[s], p, acc0);
        acc1 = fma2(c_consts.h1[s], p, acc1);
    }
#pragma unroll
    for (int i = 0; i < NQ; ++i) {
        const int m = 8 >> i;
        u64 y;
        bool first = true;
#pragma unroll
        for (int s = 0; s < 16; ++s) {
            if (!(s & m)) {
                if (first) { y = mul2(a[s], a[s | m]); first = false; }
                else       { y = fma2(a[s], a[s | m], y); }
            }
        }
        acc0 = fma2(c_consts.v0[i], y, acc0);
        acc1 = fma2(c_consts.v1[i], y, acc1);
    }

    float o0a, o0b, o1a, o1b;
    unpk2(acc0, o0a, o0b);
    unpk2(acc1, o1a, o1b);
    return make_float4(o0a, o1a, o0b, o1b);
}

// Persistent grid-stride kernel with next-iteration prefetch.
__global__ __launch_bounds__(256)
void sim_kernel(const float4* __restrict__ x, float4* __restrict__ out, int Bpair) {
    const int stride = gridDim.x * blockDim.x;
    int idx = blockIdx.x * blockDim.x + threadIdx.x;
    if (idx >= Bpair) return;

    // Prologue load.
    float4 xa = x[2 * idx];
    float4 xb = x[2 * idx + 1];

    while (true) {
        int nidx = idx + stride;
        float4 nxa, nxb;
        bool more = (nidx < Bpair);
        if (more) {                 // prefetch next pair (independent of compute below)
            nxa = x[2 * nidx];
            nxb = x[2 * nidx + 1];
        }

        out[idx] = sim_pair(xa, xb);

        if (!more) break;
        xa = nxa;
        xb = nxb;
        idx = nidx;
    }
}

extern "C" void kernel_launch(void* const* d_in, const int* in_sizes, int n_in,
                              void* d_out, int out_size) {
    const float* x       = (const float*)d_in[0];  // (B, 4)
    const float* weights = (const float*)d_in[1];  // (2, 4)
    const float* W       = (const float*)d_in[2];  // (2, 4)
    const float* b       = (const float*)d_in[3];  // (2,)

    int B = in_sizes[0] / NQ;
    int Bpair = B / 2;

    setup_kernel<<<1, 32>>>(weights, W, b);

    void* dst = nullptr;
    void* src = nullptr;
    cudaGetSymbolAddress(&dst, c_consts);
    cudaGetSymbolAddress(&src, g_scratch);
    cudaMemcpyAsync(dst, src, sizeof(Consts), cudaMemcpyDeviceToDevice, 0);

    // One resident wave: 4 blocks/SM x 148 SMs (regs ~44-52 -> 4 blocks fit).
    int blocks = 592;
    int maxBlocks = (Bpair + 255) / 256;
    if (blocks > maxBlocks) blocks = maxBlocks;
    sim_kernel<<<blocks, 256>>>((const float4*)x, (float4*)d_out, Bpair);
}